// round 13
// baseline (speedup 1.0000x reference)
#include <cuda_runtime.h>
#include <cuda_bf16.h>
#include <cstdint>
#include <math.h>

// ---------------- scratch (static device globals; no runtime alloc) ----------
__device__ float g_qkv[2 * 2048 * 3072];        // [B,N,3C] fp32
__device__ float g_vsum[32 * 64];
__device__ float g_vsum_p[32 * 16 * 64];
// packed tiled bf16 operands: tile(rt,kt) = 128 rows x 32 cols, SW64-swizzled,
// 8192 B contiguous; tile index = rt*(K/32)+kt
__device__ __nv_bfloat16 g_xh[4096 * 1024], g_xl[4096 * 1024];
__device__ __nv_bfloat16 g_w1h[3072 * 1024], g_w1l[3072 * 1024];
__device__ __nv_bfloat16 g_w2h[1024 * 1024], g_w2l[1024 * 1024];
__device__ __nv_bfloat16 g_ah[4096 * 1024], g_al[4096 * 1024];

__device__ __forceinline__ unsigned short bfbits(__nv_bfloat16 v) {
    return *reinterpret_cast<unsigned short*>(&v);
}

// ---------------- fp32 -> bf16 hi/lo split INTO packed tiled layout ----------
__global__ void split_pack(const float* __restrict__ src,
                           __nv_bfloat16* __restrict__ hi,
                           __nv_bfloat16* __restrict__ lo, int n4) {
    int i = blockIdx.x * 256 + threadIdx.x;
    if (i >= n4) return;
    const int r = i >> 8;
    const int c4 = (i & 255) << 2;
    float4 v = reinterpret_cast<const float4*>(src)[i];
    float vv[4] = {v.x, v.y, v.z, v.w};
    unsigned short hb[4], lb[4];
    #pragma unroll
    for (int j = 0; j < 4; j++) {
        __nv_bfloat16 h = __float2bfloat16_rn(vv[j]);
        __nv_bfloat16 l = __float2bfloat16_rn(vv[j] - __bfloat162float(h));
        hb[j] = bfbits(h); lb[j] = bfbits(l);
    }
    const int rt = r >> 7, rowin = r & 127;
    const int kt = c4 >> 5, colin = c4 & 31;
    uint32_t off = (uint32_t)rowin * 64 + (uint32_t)colin * 2;
    uint32_t sw = off ^ ((off >> 3) & 0x30);
    size_t dst = ((size_t)(rt * 32 + kt)) * 4096 + (sw >> 1);
    *reinterpret_cast<ushort4*>(hi + dst) = make_ushort4(hb[0], hb[1], hb[2], hb[3]);
    *reinterpret_cast<ushort4*>(lo + dst) = make_ushort4(lb[0], lb[1], lb[2], lb[3]);
}

// =============================================================================
// tcgen05 cg2 GEMM: 4-CTA cluster computes 512x256 tile as two cg2 pairs that
// SHARE the B tile via cp.async.bulk multicast. K-chunk 32; 5-stage ring;
// warp-specialized control (producer warp1, consumer/forwarder warp0).
// =============================================================================
#define NSTG 5
#define STG_B 32768
#define GEMM_TC_SMEM (2048 + NSTG * STG_B)

#if defined(__CUDA_ARCH__) && defined(__CUDA_ARCH_FEAT_SM103_ALL)
__device__ __forceinline__ uint32_t elect1() {
    uint32_t p;
    asm volatile("{\n\t.reg .pred p;\n\telect.sync _|p, 0xFFFFFFFF;\n\tselp.b32 %0,1,0,p;\n\t}"
                 : "=r"(p));
    return p;
}
__device__ __forceinline__ uint64_t make_desc_sw64(uint32_t addr) {
    return ((uint64_t)4 << 61) | ((uint64_t)1 << 46) | ((uint64_t)32 << 32) |
           ((uint64_t)1 << 16) | (uint64_t)((addr >> 4) & 0x3FFF);
}
__device__ __forceinline__ void mma_f16_ss_cg2(uint32_t d, uint64_t a, uint64_t b,
                                               uint32_t idesc, uint32_t acc) {
    asm volatile(
        "{\n\t.reg .pred p;\n\tsetp.ne.u32 p, %4, 0;\n\t"
        "tcgen05.mma.cta_group::2.kind::f16 [%0], %1, %2, %3, "
        "{%5,%5,%5,%5,%5,%5,%5,%5}, p;\n\t}"
        :: "r"(d), "l"(a), "l"(b), "r"(idesc), "r"(acc), "r"(0u) : "memory");
}
__device__ __forceinline__ void bulk_g2s(uint32_t dst, const void* src,
                                         uint32_t bytes, uint32_t mbar) {
    asm volatile(
        "cp.async.bulk.shared::cluster.global.mbarrier::complete_tx::bytes "
        "[%0], [%1], %2, [%3];"
        :: "r"(dst), "l"(src), "r"(bytes), "r"(mbar) : "memory");
}
__device__ __forceinline__ void bulk_g2s_mc(uint32_t dst, const void* src,
                                            uint32_t bytes, uint32_t mbar,
                                            unsigned short mask) {
    asm volatile(
        "cp.async.bulk.shared::cluster.global.mbarrier::complete_tx::bytes.multicast::cluster "
        "[%0], [%1], %2, [%3], %4;"
        :: "r"(dst), "l"(src), "r"(bytes), "r"(mbar), "h"(mask) : "memory");
}
#define MBAR_INIT(a, c) \
    asm volatile("mbarrier.init.shared.b64 [%0], %1;" :: "r"(a), "r"(c) : "memory")
#define MBAR_EXPECT_TX(a, bytes) \
    asm volatile("mbarrier.arrive.expect_tx.shared.b64 _, [%0], %1;" \
                 :: "r"(a), "r"(bytes) : "memory")
#define MBAR_WAIT(a, ph) do {                                                   \
    uint32_t _done = 0;                                                         \
    while (!_done) {                                                            \
        asm volatile(                                                           \
            "{\n\t.reg .pred p;\n\t"                                            \
            "mbarrier.try_wait.parity.acquire.cta.shared::cta.b64 p, [%1], %2, 0x989680;\n\t" \
            "selp.b32 %0,1,0,p;\n\t}"                                           \
            : "=r"(_done) : "r"(a), "r"((uint32_t)(ph)) : "memory");            \
    }                                                                           \
} while (0)
#define MBAR_ARRIVE_TO(trank, localaddr) \
    asm volatile( \
        "{\n\t.reg .b32 ra;\n\tmapa.shared::cluster.u32 ra, %0, %1;\n\t" \
        "mbarrier.arrive.shared::cluster.b64 _, [ra];\n\t}" \
        :: "r"(localaddr), "r"(trank) : "memory")
#define TC_COMMIT_MC2(mb, mask) \
    asm volatile("tcgen05.commit.cta_group::2.mbarrier::arrive::one.shared::cluster.multicast::cluster.b64 [%0], %1;" \
                 :: "r"(mb), "h"((unsigned short)(mask)) : "memory")
#define TC_LD_X32(r, addr)                                                      \
    asm volatile("tcgen05.ld.sync.aligned.32x32b.x32.b32 "                      \
        "{%0,%1,%2,%3,%4,%5,%6,%7,%8,%9,%10,%11,%12,%13,%14,%15,"              \
        "%16,%17,%18,%19,%20,%21,%22,%23,%24,%25,%26,%27,%28,%29,%30,%31}, [%32];" \
        : "=r"((r)[0]),"=r"((r)[1]),"=r"((r)[2]),"=r"((r)[3]),                  \
          "=r"((r)[4]),"=r"((r)[5]),"=r"((r)[6]),"=r"((r)[7]),                  \
          "=r"((r)[8]),"=r"((r)[9]),"=r"((r)[10]),"=r"((r)[11]),                \
          "=r"((r)[12]),"=r"((r)[13]),"=r"((r)[14]),"=r"((r)[15]),              \
          "=r"((r)[16]),"=r"((r)[17]),"=r"((r)[18]),"=r"((r)[19]),              \
          "=r"((r)[20]),"=r"((r)[21]),"=r"((r)[22]),"=r"((r)[23]),              \
          "=r"((r)[24]),"=r"((r)[25]),"=r"((r)[26]),"=r"((r)[27]),              \
          "=r"((r)[28]),"=r"((r)[29]),"=r"((r)[30]),"=r"((r)[31])               \
        : "r"(addr))
#define CLUSTER_SYNC_() do { \
    asm volatile("barrier.cluster.arrive.aligned;" ::: "memory"); \
    asm volatile("barrier.cluster.wait.aligned;" ::: "memory"); \
} while (0)
#endif

__global__ __launch_bounds__(128, 1) __cluster_dims__(4, 1, 1)
void gemm_tc(const __nv_bfloat16* __restrict__ Ah_, const __nv_bfloat16* __restrict__ Al_,
             const __nv_bfloat16* __restrict__ Bh_, const __nv_bfloat16* __restrict__ Bl_,
             const float* __restrict__ bias, float* __restrict__ C, int N, int K) {
#if defined(__CUDA_ARCH__) && defined(__CUDA_ARCH_FEAT_SM103_ALL)
    extern __shared__ char smem[];
    const int tid = threadIdx.x;
    const int wid = tid >> 5, lane = tid & 31;
    const int rank = blockIdx.x & 3;                // cluster rank 0..3
    const int ntile = blockIdx.x >> 2;
    const int bn = ntile * 256;
    const int pair = rank >> 1;                     // 0 or 1
    const int bm = blockIdx.y * 512 + pair * 256 + (rank & 1) * 128;
    const uint32_t sbase = (uint32_t)__cvta_generic_to_shared(smem);
    const uint32_t tiles0 = (sbase + 1024 + 1023) & ~1023u;
    const uint32_t full0 = sbase + 64, done0 = sbase + 128;
    const uint32_t rdy0 = sbase + 192, bready0 = sbase + 256, mbfin = sbase + 320;

    if (tid == 0) {
        #pragma unroll
        for (int s = 0; s < NSTG; s++) {
            MBAR_INIT(full0 + 8 * s, 1);
            MBAR_INIT(done0 + 8 * s, 1);
            MBAR_INIT(rdy0 + 8 * s, 1);
            MBAR_INIT(bready0 + 8 * s, 1);
        }
        MBAR_INIT(mbfin, 1);
    }
    if (wid == 0) {
        asm volatile("tcgen05.alloc.cta_group::2.sync.aligned.shared::cta.b32 [%0], %1;"
                     :: "r"(sbase), "r"(256u) : "memory");
    }
    __syncthreads();
    uint32_t tmem;
    asm volatile("ld.shared.b32 %0, [%1];" : "=r"(tmem) : "r"(sbase));

    CLUSTER_SYNC_();

    const int nkt = K >> 5;
    const uint32_t idesc = 0x10400490u;      // f32 d, bf16 a/b, M=256, N=256

    if (wid == 1 && elect1()) {
        // ---------------- producer (every rank): A local; B via multicast ------
        const int rtA = blockIdx.y * 4 + rank;
        const __nv_bfloat16* tAh = Ah_ + (size_t)rtA * nkt * 4096;
        const __nv_bfloat16* tAl = Al_ + (size_t)rtA * nkt * 4096;
        const int rtB = ntile * 2 + (rank & 1);
        const __nv_bfloat16* tBh = Bh_ + (size_t)rtB * nkt * 4096;
        const __nv_bfloat16* tBl = Bl_ + (size_t)rtB * nkt * 4096;
        const unsigned short bmask = (rank & 1) ? 0xA : 0x5;   // {1,3} or {0,2}

        for (int j = 0; j < nkt; j++) {
            const int s = j % NSTG;
            const int ph = (j / NSTG) & 1;
            if (j >= NSTG) {
                MBAR_WAIT(done0 + 8 * s, ph ^ 1);
            }
            const uint32_t sb = tiles0 + (uint32_t)s * STG_B;
            const uint32_t mb = full0 + 8 * s;
            MBAR_EXPECT_TX(mb, (uint32_t)STG_B);
            bulk_g2s(sb,        tAh + (size_t)j * 4096, 8192, mb);
            bulk_g2s(sb + 8192, tAl + (size_t)j * 4096, 8192, mb);
            if (rank < 2) {
                // wait partner pair's readiness before overwriting their B copy
                MBAR_WAIT(bready0 + 8 * s, ph);
                bulk_g2s_mc(sb + 16384, tBh + (size_t)j * 4096, 8192, mb, bmask);
                bulk_g2s_mc(sb + 24576, tBl + (size_t)j * 4096, 8192, mb, bmask);
            } else {
                MBAR_ARRIVE_TO(rank - 2, bready0 + 8 * s);
            }
        }
    } else if (wid == 0 && elect1()) {
        if ((rank & 1) == 0) {
            // ---------------- pair leader: MMA stream -------------------------
            const unsigned short pmask = (unsigned short)(0x3 << (pair * 2));
            for (int kt = 0; kt < nkt; kt++) {
                const int s = kt % NSTG;
                const int ph = (kt / NSTG) & 1;
                MBAR_WAIT(full0 + 8 * s, ph);
                MBAR_WAIT(rdy0 + 8 * s, ph);
                const uint32_t sb = tiles0 + (uint32_t)s * STG_B;
                const uint64_t dAh = make_desc_sw64(sb);
                const uint64_t dAl = make_desc_sw64(sb + 8192);
                const uint64_t dBh = make_desc_sw64(sb + 16384);
                const uint64_t dBl = make_desc_sw64(sb + 24576);
                #pragma unroll
                for (int k = 0; k < 2; k++) {
                    const uint64_t o = 2 * k;
                    const uint32_t acc0 = (kt == 0 && k == 0) ? 0u : 1u;
                    mma_f16_ss_cg2(tmem, dAh + o, dBh + o, idesc, acc0);
                    mma_f16_ss_cg2(tmem, dAh + o, dBl + o, idesc, 1u);
                    mma_f16_ss_cg2(tmem, dAl + o, dBh + o, idesc, 1u);
                }
                TC_COMMIT_MC2(done0 + 8 * s, pmask);
                if (kt == nkt - 1) TC_COMMIT_MC2(mbfin, pmask);
            }
        } else {
            // ---------------- odd rank: forward full[s] -> leader rdy[s] ------
            for (int kt = 0; kt < nkt; kt++) {
                const int s = kt % NSTG;
                const int ph = (kt / NSTG) & 1;
                MBAR_WAIT(full0 + 8 * s, ph);
                MBAR_ARRIVE_TO(rank - 1, rdy0 + 8 * s);
            }
        }
    }

    MBAR_WAIT(mbfin, 0);
    asm volatile("tcgen05.fence::after_thread_sync;" ::: "memory");
    __syncthreads();

    // epilogue: each CTA reads its own 128 lanes x 256 cols
    {
        const int row = bm + wid * 32 + lane;
        float* Cr = C + (size_t)row * N + bn;
        for (int g = 0; g < 8; g++) {
            uint32_t r[32];
            TC_LD_X32(r, tmem + g * 32);
            asm volatile("tcgen05.wait::ld.sync.aligned;" ::: "memory");
            #pragma unroll
            for (int j = 0; j < 32; j += 4) {
                float4 o;
                o.x = __uint_as_float(r[j + 0]);
                o.y = __uint_as_float(r[j + 1]);
                o.z = __uint_as_float(r[j + 2]);
                o.w = __uint_as_float(r[j + 3]);
                if (bias) {
                    const float4 b4 = *reinterpret_cast<const float4*>(bias + bn + g * 32 + j);
                    o.x += b4.x; o.y += b4.y; o.z += b4.z; o.w += b4.w;
                }
                *reinterpret_cast<float4*>(Cr + g * 32 + j) = o;
            }
        }
        asm volatile("tcgen05.fence::before_thread_sync;" ::: "memory");
    }
    __syncthreads();
    if (wid == 0) {
        asm volatile("tcgen05.relinquish_alloc_permit.cta_group::2.sync.aligned;");
        asm volatile("tcgen05.dealloc.cta_group::2.sync.aligned.b32 %0, %1;"
                     :: "r"(tmem), "r"(256u));
    }
    CLUSTER_SYNC_();
#endif
}

// ---------------- V row-sum (2-stage) ----------------------------------------
__global__ void vsum_partial() {
    const int N = 2048, C3 = 3072, Dh = 64, H = 16;
    const int bh = blockIdx.x, s = blockIdx.y;
    const int b = bh / H, h = bh % H;
    const int dh = threadIdx.x;
    const float* base = g_qkv + (size_t)(b * N) * C3 + 2048 + h * Dh + dh;
    float acc = 0.0f;
    const int n0 = s * 128;
    for (int n = n0; n < n0 + 128; n++) acc += base[(size_t)n * C3];
    g_vsum_p[(bh * 16 + s) * Dh + dh] = acc;
}
__global__ void vsum_reduce() {
    const int Dh = 64;
    const int bh = blockIdx.x, dh = threadIdx.x;
    float acc = 0.0f;
    #pragma unroll
    for (int s = 0; s < 16; s++) acc += g_vsum_p[(bh * 16 + s) * Dh + dh];
    g_vsum[bh * Dh + dh] = acc;
}

// ---------------- banded attention: writes packed bf16 hi/lo -----------------
__global__ __launch_bounds__(256)
void band_attn(const int* __restrict__ epoch_p) {
    const int N = 2048, H = 16, C3 = 3072;
    const int w = (*epoch_p < 15) ? 16 : 20;

    __shared__ float sK[48 * 64];
    __shared__ float sV[48 * 64];

    const int tid = threadIdx.x;
    const int g = blockIdx.x;
    const int n0 = (g & 255) * 8;
    const int bh = g >> 8;
    const int b = bh >> 4, h = bh & 15;

    const int lo = max(0, n0 - w);
    const int hi = min(N - 1, n0 + 7 + w);
    const int rows = hi - lo + 1;

    const float* base = g_qkv + (size_t)(b * N + lo) * C3 + 1024 + h * 64;
    for (int idx = tid; idx < rows * 16; idx += 256) {
        const int r = idx >> 4, c4 = (idx & 15) * 4;
        *reinterpret_cast<float4*>(&sK[r * 64 + c4]) =
            *reinterpret_cast<const float4*>(base + (size_t)r * C3 + c4);
        *reinterpret_cast<float4*>(&sV[r * 64 + c4]) =
            *reinterpret_cast<const float4*>(base + (size_t)r * C3 + 1024 + c4);
    }
    __syncthreads();

    const int wid = tid >> 5, lane = tid & 31;
    const int n = n0 + wid;

    const float* qp = g_qkv + (size_t)(b * N + n) * C3 + h * 64;
    const float q0 = qp[lane], q1 = qp[lane + 32];
    const float s0 = g_vsum[bh * 64 + lane];
    const float s1 = g_vsum[bh * 64 + lane + 32];

    const int m0 = max(0, n - w);
    const int m1 = min(N - 1, n + w);

    float Mx = -INFINITY, Z = 0.0f;
    float a0 = 0.0f, a1 = 0.0f, bv0 = 0.0f, bv1 = 0.0f;

    for (int m = m0; m <= m1; m++) {
        const int r = m - lo;
        const float k0 = sK[r * 64 + lane], k1 = sK[r * 64 + lane + 32];
        const float v0 = sV[r * 64 + lane], v1 = sV[r * 64 + lane + 32];

        float p = q0 * k0 + q1 * k1;
        p += __shfl_xor_sync(0xffffffffu, p, 16);
        p += __shfl_xor_sync(0xffffffffu, p, 8);
        p += __shfl_xor_sync(0xffffffffu, p, 4);
        p += __shfl_xor_sync(0xffffffffu, p, 2);
        p += __shfl_xor_sync(0xffffffffu, p, 1);
        const float l = p * 4.0f;   // scale = Dh // H = 4

        if (l > Mx) {
            const float f = __expf(Mx - l);
            Z *= f; a0 *= f; a1 *= f;
            Mx = l;
        }
        const float e = __expf(l - Mx);
        Z += e;
        a0 = fmaf(e, v0, a0);
        a1 = fmaf(e, v1, a1);
        bv0 += v0; bv1 += v1;
    }

    const float lm = 1e-9f;
    const float cu = __expf(lm - Mx);
    const int nband = m1 - m0 + 1;
    Z += (float)(N - nband) * cu;

    const float invZ = 1.0f / Z;
    const float o0 = (a0 + cu * (s0 - bv0)) * invZ;
    const float o1 = (a1 + cu * (s1 - bv1)) * invZ;

    const int rr = b * N + n;
    const int rt = rr >> 7, rowin = rr & 127;
    uint32_t off = (uint32_t)rowin * 64 + (uint32_t)lane * 2;
    uint32_t sw = off ^ ((off >> 3) & 0x30);
    const size_t t0 = ((size_t)(rt * 32 + 2 * h)) * 4096 + (sw >> 1);
    const size_t t1 = ((size_t)(rt * 32 + 2 * h + 1)) * 4096 + (sw >> 1);

    __nv_bfloat16 h0 = __float2bfloat16_rn(o0);
    __nv_bfloat16 l0 = __float2bfloat16_rn(o0 - __bfloat162float(h0));
    __nv_bfloat16 h1 = __float2bfloat16_rn(o1);
    __nv_bfloat16 l1 = __float2bfloat16_rn(o1 - __bfloat162float(h1));
    g_ah[t0] = h0;  g_al[t0] = l0;
    g_ah[t1] = h1;  g_al[t1] = l1;
}

// ---------------- launcher ---------------------------------------------------
extern "C" void kernel_launch(void* const* d_in, const int* in_sizes, int n_in,
                              void* d_out, int out_size) {
    const float* x      = (const float*)d_in[0];
    const float* qkv_w  = (const float*)d_in[1];
    const float* proj_w = (const float*)d_in[2];
    const float* proj_b = (const float*)d_in[3];
    const int*   epoch  = (const int*)d_in[4];

    float* qkv_buf;
    __nv_bfloat16 *xh, *xl, *w1h, *w1l, *w2h, *w2l, *ah, *al;
    cudaGetSymbolAddress((void**)&qkv_buf, g_qkv);
    cudaGetSymbolAddress((void**)&xh, g_xh);   cudaGetSymbolAddress((void**)&xl, g_xl);
    cudaGetSymbolAddress((void**)&w1h, g_w1h); cudaGetSymbolAddress((void**)&w1l, g_w1l);
    cudaGetSymbolAddress((void**)&w2h, g_w2h); cudaGetSymbolAddress((void**)&w2l, g_w2l);
    cudaGetSymbolAddress((void**)&ah, g_ah);   cudaGetSymbolAddress((void**)&al, g_al);

    cudaFuncSetAttribute(gemm_tc, cudaFuncAttributeMaxDynamicSharedMemorySize, GEMM_TC_SMEM);

    // 1) split inputs to packed tiled bf16 hi/lo
    {
        int n4 = 4096 * 256;
        split_pack<<<(n4 + 255) / 256, 256>>>(x, xh, xl, n4);
        n4 = 3072 * 256;
        split_pack<<<(n4 + 255) / 256, 256>>>(qkv_w, w1h, w1l, n4);
        n4 = 1024 * 256;
        split_pack<<<(n4 + 255) / 256, 256>>>(proj_w, w2h, w2l, n4);
    }

    // 2) qkv = x @ qkv_w^T : 4-CTA clusters, 512x256 per cluster (B multicast)
    gemm_tc<<<dim3(4 * (3072 / 256), 4096 / 512), 128, GEMM_TC_SMEM>>>(
        xh, xl, w1h, w1l, nullptr, qkv_buf, 3072, 1024);

    // 3) V row sums
    {
        dim3 g1(32, 16);
        vsum_partial<<<g1, 64>>>();
        vsum_reduce<<<32, 64>>>();
    }

    // 4) banded attention -> packed bf16 hi/lo att
    band_attn<<<32 * 256, 256>>>(epoch);

    // 5) out = att @ proj_w^T + proj_b : 4-CTA clusters
    gemm_tc<<<dim3(4 * (1024 / 256), 4096 / 512), 128, GEMM_TC_SMEM>>>(
        ah, al, w2h, w2l, proj_b, (float*)d_out, 1024, 1024);
}